// round 16
// baseline (speedup 1.0000x reference)
#include <cuda_runtime.h>
#include <stdint.h>
#include <math.h>

#define T_FRAMES   3000
#define F_BINS     201
#define FROW       402                  // floats per frame
#define BATCH      32
#define CHUNK      231
#define CHUNKS     13                   // 13*231 = 3003 >= 3000; grid 416 <= 444
#define NTHREADS   224
#define NWARPS     7
#define EPS_F      1e-5f
#define LOG10_2    0.30102999566398f
#define SUBF       (10 * FROW)          // floats per 10-frame sub-buffer (4020)
#define SUBB       (SUBF * 4)           // bytes (16080)
#define SUBCH      (SUBB / 16)          // 16B chunks (1005)
#define BUFN       (5 * NTHREADS)       // float2 contrib pairs in the tile
#define SMEM_BYTES (4 * SUBB + BUFN * 8)   // 64320 + 8960 = 73280

__device__ __forceinline__ void cp_async16(uint32_t s, const float* g) {
  asm volatile("cp.async.ca.shared.global [%0], [%1], 16;\n" :: "r"(s), "l"(g));
}
#define CP_COMMIT() asm volatile("cp.async.commit_group;\n" ::: "memory")
#define CP_WAIT1()  asm volatile("cp.async.wait_group 1;\n" ::: "memory")

// Cooperative fill of one 10-frame sub-buffer: 1005 x 16B chunks over 224
// threads. Sub-buffer start frames are even -> 16B-aligned sources. Per-chunk
// clamp to the last 16B of x keeps every fill in-bounds (clamped data only
// reaches frames whose outputs are masked).
#define FILL10(DST_U32, SRC_PTR)                                                 \
  do {                                                                           \
    const float* gb_ = (SRC_PTR);                                                \
    _Pragma("unroll")                                                            \
    for (int i_ = 0; i_ < 5; i_++) {                                             \
      const int ch_ = tid + i_ * NTHREADS;                                       \
      if (ch_ < SUBCH) {                                                         \
        const float* p_ = gb_ + 4 * ch_;                                         \
        if (p_ > xlim) p_ = xlim;                                                \
        cp_async16((DST_U32) + 16 * ch_, p_);                                    \
      }                                                                          \
    }                                                                            \
    CP_COMMIT();                                                                 \
  } while (0)

// Per-frame scan math. J (ring index) / LJ (sub-buffer frame 0..9) are
// compile-time after unroll. Only TWO logs per frame: the welch birth log is
// remembered in ring_lw (fp32, exact) instead of being recomputed at
// eviction. The 10-frame s eviction is recomputed from the PREVIOUS
// sub-buffer's raw x data (still resident in smem; bitwise-identical).
// SEV: s-eviction active. WEV: 30-window eviction active. T0CHK guards t==0.
#define FRAME_MATH(J, LJ, RC10, RC30, RC30LM, SEV, WEV, T0CHK, OUTV)             \
  do {                                                                           \
    const float2 xv = *(const float2*)(cur_p + (LJ) * FROW + foff);              \
    const float s_t = fmaf(xv.y, xv.y, xv.x * xv.x) * Cf;                        \
    float we_t = fmaf(sum_s, (RC10), EPS_F);                                     \
    if (T0CHK) we_t = t0block ? EPS_F : we_t;                                    \
    const float lw2_t = __log2f(we_t);                                           \
    {                                                                            \
      const float am = sum_we * (RC30);                                          \
      OUTV = fmaf(__log2f(am), L10m, -(sum_lw2 * (RC30LM)));                     \
      if (T0CHK) OUTV = t0block ? 0.f : OUTV;                                    \
    }                                                                            \
    if (WEV) {                                                                   \
      sum_we  += we_t  - ring_w[(J) % 30];                                       \
      sum_lw2 += lw2_t - ring_lw[(J) % 30];                                      \
    } else {                                                                     \
      sum_we  += we_t;                                                           \
      sum_lw2 += lw2_t;                                                          \
    }                                                                            \
    ring_w[(J) % 30]  = we_t;                                                    \
    ring_lw[(J) % 30] = lw2_t;                                                   \
    if (SEV) {                                                                   \
      const float2 xo = *(const float2*)(prv_p + (LJ) * FROW + foff);            \
      sum_s += s_t - fmaf(xo.y, xo.y, xo.x * xo.x) * Cf;                         \
    } else {                                                                     \
      sum_s += s_t;                                                              \
    }                                                                            \
  } while (0)

// Consume 10 steady frames (5 pairs) into the contrib tile via STS.64.
#define CONSUME_STEADY(J0)                                                       \
  do {                                                                           \
    _Pragma("unroll")                                                            \
    for (int p_ = 0; p_ < 5; p_++) {                                             \
      float cA_, cB_;                                                            \
      FRAME_MATH((J0)+2*p_,   2*p_,   0.1f, (1.0f/30.0f), rc30Lm, 1, 1, false, cA_); \
      FRAME_MATH((J0)+2*p_+1, 2*p_+1, 0.1f, (1.0f/30.0f), rc30Lm, 1, 1, false, cB_); \
      if (es_) buf2[p_ * NTHREADS + tid] = make_float2(cA_, cB_);                \
    }                                                                            \
  } while (0)

// First warm sub-group (frames 0..9 of the scan): no evictions, full ramps.
#define CONSUME_WARM0()                                                          \
  do {                                                                           \
    _Pragma("unroll")                                                            \
    for (int p_ = 0; p_ < 5; p_++) {                                             \
      const int jA_ = 2 * p_, jB_ = jA_ + 1;                                     \
      const float rc10A_ = 1.0f / (float)((jA_ < 1) ? 1 : jA_);                  \
      const float rc30A_ = rc10A_;                                               \
      const float rc10B_ = 1.0f / (float)jB_;                                    \
      const float rc30B_ = rc10B_;                                               \
      float cA_, cB_;                                                            \
      FRAME_MATH(jA_, 2*p_,   rc10A_, rc30A_, rc30A_ * L10m, 0, 0, (jA_==0), cA_); \
      FRAME_MATH(jB_, 2*p_+1, rc10B_, rc30B_, rc30B_ * L10m, 0, 0, false, cB_);  \
      if (es_) buf2[p_ * NTHREADS + tid] = make_float2(cA_, cB_);                \
    }                                                                            \
  } while (0)

// Warm sub-groups 2-3 (frames 10..29): s-eviction active (prev sub-buffer
// holds the needed x rows), 30-window still growing (1/j ramp, no eviction).
#define CONSUME_WARM_SE(J0)                                                      \
  do {                                                                           \
    _Pragma("unroll")                                                            \
    for (int p_ = 0; p_ < 5; p_++) {                                             \
      const int jA_ = (J0) + 2 * p_, jB_ = jA_ + 1;                              \
      const float rc30A_ = 1.0f / (float)jA_;                                    \
      const float rc30B_ = 1.0f / (float)jB_;                                    \
      float cA_, cB_;                                                            \
      FRAME_MATH(jA_, 2*p_,   0.1f, rc30A_, rc30A_ * L10m, 1, 0, false, cA_);    \
      FRAME_MATH(jB_, 2*p_+1, 0.1f, rc30B_, rc30B_ * L10m, 1, 0, false, cB_);    \
      if (es_) buf2[p_ * NTHREADS + tid] = make_float2(cA_, cB_);                \
    }                                                                            \
  } while (0)

// Reduce 5 contrib pairs (warps 0-4, one pair each); writes masked to
// [chunk_start, chunk_end).
#define REDUCE5(TB)                                                              \
  do {                                                                           \
    if (warp < 5) {                                                              \
      float vx_ = 0.f, vy_ = 0.f;                                                \
      _Pragma("unroll")                                                          \
      for (int i_ = 0; i_ < 7; i_++) {                                           \
        const float2 u_ = buf2[warp * NTHREADS + lane + 32 * i_];                \
        vx_ += u_.x; vy_ += u_.y;                                                \
      }                                                                          \
      _Pragma("unroll")                                                          \
      for (int o_ = 16; o_ > 0; o_ >>= 1) {                                      \
        vx_ += __shfl_xor_sync(0xffffffffu, vx_, o_);                            \
        vy_ += __shfl_xor_sync(0xffffffffu, vy_, o_);                            \
      }                                                                          \
      if (lane == 0) {                                                           \
        const int tA_ = (TB) + 2 * warp;                                         \
        if (tA_ >= chunk_start && tA_ < chunk_end)                               \
          out[(size_t)b * T_FRAMES + tA_] = vx_;                                 \
        if (tA_ + 1 >= chunk_start && tA_ + 1 < chunk_end)                       \
          out[(size_t)b * T_FRAMES + tA_ + 1] = vy_;                             \
      }                                                                          \
    }                                                                            \
  } while (0)

// One sub-group: CHAMPION (round-13) protocol — fill at start, TWO barriers —
// on a 4-slot buffer ring. Roles: o0 = cur (consume), o3 = prev (s-eviction
// reads), o2 = fill target (frames ts+20; that slot's last reader was the
// previous subgroup's eviction). CP_WAIT1 completes the fill issued ONE
// subgroup ago (next cur) while leaving this subgroup's fill in flight
// (2-subgroup lookahead). Fill is UNCONDITIONAL so the outstanding-group
// count stays constant (WAIT1 correctness depends on it).
#define SUBGROUP(CONSUME_CALL, TS)                                               \
  do {                                                                           \
    const int ts_ = (TS);                                                        \
    const bool es_ = (ts_ + 9 >= chunk_start) && (ts_ < chunk_end);              \
    const float* cur_p = stage + o0;                                             \
    const float* prv_p = stage + o3;                                             \
    FILL10(stage_a + 4u * (uint32_t)o2, xb + (size_t)(ts_ + 20) * FROW);         \
    CONSUME_CALL;                                                                \
    CP_WAIT1();                                                                  \
    __syncthreads();                                                             \
    if (es_) REDUCE5(ts_);                                                       \
    __syncthreads();                                                             \
    { const int t_ = o0; o0 = o1; o1 = o2; o2 = o3; o3 = t_; }                   \
  } while (0)

__global__ __launch_bounds__(NTHREADS, 3)
void ltsf_kernel(const float* __restrict__ x, float* __restrict__ out,
                 const float cA) {
  extern __shared__ float dsm[];
  float*  stage = dsm;                          // four 10-frame sub-buffers
  float2* buf2  = (float2*)(dsm + 4 * SUBF);    // contrib tile

  const int unit = blockIdx.x;
  const int b = unit / CHUNKS;
  const int c = unit % CHUNKS;
  const int chunk_start = c * CHUNK;
  const int chunk_end = min(chunk_start + CHUNK, T_FRAMES);
  // >= 40 frames of halo, rounded DOWN to even (16B alignment of sub-buffers)
  const int t_begin = (c == 0) ? 0 : ((chunk_start - 40) & ~1);
  const bool t0block = (c == 0);

  const int tid  = threadIdx.x;
  const int f    = tid;
  const bool active = (f < F_BINS);
  const int lane = tid & 31;
  const int warp = tid >> 5;

  // per-bin scale: interior bins doubled (welch one-sided spectrum)
  const float Cf = (f == 0 || f == F_BINS - 1) ? cA : 2.0f * cA;
  const float L10m   = active ? LOG10_2 : 0.f;  // masks inactive contribs to 0
  const float rc30Lm = L10m * (1.0f / 30.0f);

  const int fsel = active ? f : 0;
  const int foff = 2 * fsel;
  const float* xb   = x + (size_t)b * T_FRAMES * FROW;
  const float* xlim = x + (size_t)BATCH * T_FRAMES * FROW - 4;  // last 16B
  const uint32_t stage_a = (uint32_t)__cvta_generic_to_shared(stage);

  // 4-slot buffer ring offsets (floats): cur, next, fill-target, prev
  int o0 = 0, o1 = SUBF, o2 = 2 * SUBF, o3 = 3 * SUBF;

  // register-resident rings (indices compile-time via full unroll)
  float ring_w[30];
  float ring_lw[30];
  float sum_s = 0.f, sum_we = 0.f, sum_lw2 = 0.f;
#pragma unroll
  for (int i = 0; i < 30; i++) { ring_w[i] = 0.f; ring_lw[i] = 0.f; }

  // ---- prologue: fill slots 0 and 1; complete slot 0, keep 1 in flight ----
  FILL10(stage_a + 4u * (uint32_t)o0, xb + (size_t)t_begin * FROW);
  FILL10(stage_a + 4u * (uint32_t)o1, xb + (size_t)(t_begin + 10) * FROW);
  CP_WAIT1();
  __syncthreads();

  // ---- warm group: frames t_begin..t_begin+29, ramp divisors ----
  SUBGROUP(CONSUME_WARM0(),      t_begin);
  SUBGROUP(CONSUME_WARM_SE(10),  t_begin + 10);
  SUBGROUP(CONSUME_WARM_SE(20),  t_begin + 20);

  // ---- steady groups (subgroups past chunk_end consume stale smem but
  //      never write: es_ is false there) ----
  for (int tb = t_begin + 30; tb < chunk_end; tb += 30) {
    SUBGROUP(CONSUME_STEADY(0),  tb);
    SUBGROUP(CONSUME_STEADY(10), tb + 10);
    SUBGROUP(CONSUME_STEADY(20), tb + 20);
  }
}

extern "C" void kernel_launch(void* const* d_in, const int* in_sizes, int n_in,
                              void* d_out, int out_size) {
  (void)in_sizes; (void)n_in; (void)out_size;
  // hamming_sq_sum(25), periodic: sum((0.54 - 0.46*cos(2*pi*k/25))^2)
  double h = 0.0;
  for (int k = 0; k < 25; k++) {
    double w = 0.54 - 0.46 * cos(2.0 * M_PI * (double)k / 25.0);
    h += w * w;
  }
  // fold the /M (spectr) and /SAMPLE_RATE (welch) into one per-bin constant
  const float cA = (float)(h / 16000.0 / 10.0);

  cudaFuncSetAttribute(ltsf_kernel,
                       cudaFuncAttributeMaxDynamicSharedMemorySize, SMEM_BYTES);

  const float* x = (const float*)d_in[0];
  float* out = (float*)d_out;
  ltsf_kernel<<<BATCH * CHUNKS, NTHREADS, SMEM_BYTES>>>(x, out, cA);
}

// round 17
// speedup vs baseline: 1.4559x; 1.4559x over previous
#include <cuda_runtime.h>
#include <stdint.h>
#include <math.h>

#define T_FRAMES   3000
#define F_BINS     201
#define FROW       402                  // floats per frame
#define BATCH      32
#define CHUNK      167
#define CHUNKS     18                   // 18*167 = 3006 >= 3000; last chunk short
#define NTHREADS   224
#define NWARPS     7
#define EPS_F      1e-5f
#define LOG10_2    0.30102999566398f
#define SUBF       (10 * FROW)          // floats per 10-frame sub-buffer (4020)
#define SUBB       (SUBF * 4)           // bytes (16080)
#define SUBCH      (SUBB / 16)          // 16B chunks (1005)
#define BUFN       (5 * NTHREADS)       // float2 contrib pairs in the tile

__device__ __forceinline__ void cp_async16(uint32_t s, const float* g) {
  asm volatile("cp.async.ca.shared.global [%0], [%1], 16;\n" :: "r"(s), "l"(g));
}
#define CP_COMMIT() asm volatile("cp.async.commit_group;\n" ::: "memory")
#define CP_WAIT0()  asm volatile("cp.async.wait_group 0;\n" ::: "memory")

// Cooperative fill of one 10-frame sub-buffer: 1005 x 16B chunks over 224
// threads. UNIFORM fast path: when the whole window is provably in-bounds
// (gb_ <= xsafe), skip the per-chunk 64-bit clamp chain entirely; the first
// four chunks per thread are unconditional (tid+672 <= 895 < 1005).
#define FILL10(DST_U32, SRC_PTR)                                                 \
  do {                                                                           \
    const float* gb_ = (SRC_PTR);                                                \
    const uint32_t d_ = (DST_U32);                                               \
    if (gb_ <= xsafe) {                                                          \
      cp_async16(d_ + 16u * (uint32_t)tid,         gb_ + 4 * tid);               \
      cp_async16(d_ + 16u * (uint32_t)(tid + 224), gb_ + 4 * (tid + 224));       \
      cp_async16(d_ + 16u * (uint32_t)(tid + 448), gb_ + 4 * (tid + 448));       \
      cp_async16(d_ + 16u * (uint32_t)(tid + 672), gb_ + 4 * (tid + 672));       \
      if (tid < SUBCH - 896)                                                     \
        cp_async16(d_ + 16u * (uint32_t)(tid + 896), gb_ + 4 * (tid + 896));     \
    } else {                                                                     \
      _Pragma("unroll")                                                          \
      for (int i_ = 0; i_ < 5; i_++) {                                           \
        const int ch_ = tid + i_ * NTHREADS;                                     \
        if (ch_ < SUBCH) {                                                       \
          const float* p_ = gb_ + 4 * ch_;                                       \
          if (p_ > xlim) p_ = xlim;                                              \
          cp_async16(d_ + 16 * ch_, p_);                                         \
        }                                                                        \
      }                                                                          \
    }                                                                            \
    CP_COMMIT();                                                                 \
  } while (0)

// Per-frame scan math. J (ring index) / LJ (sub-buffer frame 0..9) compile-
// time after unroll. EMITC is a LITERAL 0/1: contrib math is dead-code
// eliminated in the no-emit variants. Inactive threads masked by L10m==0.
// T0CHK guards the t==0 special case (warm frame 0 only).
#define FRAME_STEP(J, LJ, RC10, RC30, RC30LM, DO_SUB, T0CHK, EMITC, OUTV)        \
  do {                                                                           \
    const float2 xv = *(const float2*)(cur_p + (LJ) * FROW + foff);              \
    const float s_t = fmaf(xv.y, xv.y, xv.x * xv.x) * Cf;                        \
    float we_t = fmaf(sum_s, (RC10), EPS_F);                                     \
    if (T0CHK) we_t = t0block ? EPS_F : we_t;                                    \
    const float lw2_t = __log2f(we_t);                                           \
    if (EMITC) {                                                                 \
      const float am = sum_we * (RC30);                                          \
      OUTV = fmaf(__log2f(am), L10m, -(sum_lw2 * (RC30LM)));                     \
      if (T0CHK) OUTV = t0block ? 0.f : OUTV;                                    \
    }                                                                            \
    if (DO_SUB) {                                                                \
      const float we_old = ring_w[(J) % 30];                                     \
      sum_we  += we_t - we_old;                                                  \
      sum_lw2 += lw2_t - __log2f(we_old);                                        \
    } else {                                                                     \
      sum_we  += we_t;                                                           \
      sum_lw2 += lw2_t;                                                          \
    }                                                                            \
    ring_w[(J) % 30] = we_t;                                                     \
    sum_s += s_t - ring_s[(J) % 10];                                             \
    ring_s[(J) % 10] = s_t;                                                      \
  } while (0)

// Steady consume, emitting: contribs stored unconditionally (STS.64 pairs).
#define CONSUME_STEADY(J0)                                                       \
  do {                                                                           \
    _Pragma("unroll")                                                            \
    for (int p_ = 0; p_ < 5; p_++) {                                             \
      float cA_, cB_;                                                            \
      FRAME_STEP((J0)+2*p_,   2*p_,   0.1f, (1.0f/30.0f), rc30Lm, 1, false, 1, cA_); \
      FRAME_STEP((J0)+2*p_+1, 2*p_+1, 0.1f, (1.0f/30.0f), rc30Lm, 1, false, 1, cB_); \
      buf2[p_ * NTHREADS + tid] = make_float2(cA_, cB_);                         \
    }                                                                            \
  } while (0)

// Steady consume, no-emit: state updates only (contrib math eliminated).
#define CONSUME_STEADY_NE(J0)                                                    \
  do {                                                                           \
    float d_;                                                                    \
    _Pragma("unroll")                                                            \
    for (int p_ = 0; p_ < 5; p_++) {                                             \
      FRAME_STEP((J0)+2*p_,   2*p_,   0.1f, (1.0f/30.0f), rc30Lm, 1, false, 0, d_); \
      FRAME_STEP((J0)+2*p_+1, 2*p_+1, 0.1f, (1.0f/30.0f), rc30Lm, 1, false, 0, d_); \
    }                                                                            \
    (void)d_;                                                                    \
  } while (0)

// Warm consume (exact ramp divisors, no ring subtraction), emitting (c==0).
#define CONSUME_WARM(J0)                                                         \
  do {                                                                           \
    _Pragma("unroll")                                                            \
    for (int p_ = 0; p_ < 5; p_++) {                                             \
      const int jA_ = (J0) + 2 * p_, jB_ = jA_ + 1;                              \
      const float rc10A_ = 1.0f / (float)((jA_ < 1) ? 1 : (jA_ > 10 ? 10 : jA_));\
      const float rc30A_ = 1.0f / (float)((jA_ < 1) ? 1 : jA_);                  \
      const float rc10B_ = 1.0f / (float)((jB_ > 10) ? 10 : jB_);                \
      const float rc30B_ = 1.0f / (float)jB_;                                    \
      float cA_, cB_;                                                            \
      FRAME_STEP(jA_, 2*p_,   rc10A_, rc30A_, rc30A_ * L10m, 0, (jA_==0), 1, cA_); \
      FRAME_STEP(jB_, 2*p_+1, rc10B_, rc30B_, rc30B_ * L10m, 0, false, 1, cB_);  \
      buf2[p_ * NTHREADS + tid] = make_float2(cA_, cB_);                         \
    }                                                                            \
  } while (0)

// Warm consume, no-emit (c>0 halo): state updates only.
#define CONSUME_WARM_NE(J0)                                                      \
  do {                                                                           \
    float d_;                                                                    \
    _Pragma("unroll")                                                            \
    for (int p_ = 0; p_ < 5; p_++) {                                             \
      const int jA_ = (J0) + 2 * p_, jB_ = jA_ + 1;                              \
      const float rc10A_ = 1.0f / (float)((jA_ < 1) ? 1 : (jA_ > 10 ? 10 : jA_));\
      const float rc10B_ = 1.0f / (float)((jB_ > 10) ? 10 : jB_);                \
      FRAME_STEP(jA_, 2*p_,   rc10A_, 1.f, L10m, 0, (jA_==0), 0, d_);            \
      FRAME_STEP(jB_, 2*p_+1, rc10B_, 1.f, L10m, 0, false, 0, d_);               \
    }                                                                            \
    (void)d_;                                                                    \
  } while (0)

// Reduce 5 contrib pairs (warps 0-4, one pair each); writes masked to
// [chunk_start, chunk_end).
#define REDUCE5(TB)                                                              \
  do {                                                                           \
    if (warp < 5) {                                                              \
      float vx_ = 0.f, vy_ = 0.f;                                                \
      _Pragma("unroll")                                                          \
      for (int i_ = 0; i_ < 7; i_++) {                                           \
        const float2 u_ = buf2[warp * NTHREADS + lane + 32 * i_];                \
        vx_ += u_.x; vy_ += u_.y;                                                \
      }                                                                          \
      _Pragma("unroll")                                                          \
      for (int o_ = 16; o_ > 0; o_ >>= 1) {                                      \
        vx_ += __shfl_xor_sync(0xffffffffu, vx_, o_);                            \
        vy_ += __shfl_xor_sync(0xffffffffu, vy_, o_);                            \
      }                                                                          \
      if (lane == 0) {                                                           \
        const int tA_ = (TB) + 2 * warp;                                         \
        if (tA_ >= chunk_start && tA_ < chunk_end)                               \
          out[(size_t)b * T_FRAMES + tA_] = vx_;                                 \
        if (tA_ + 1 >= chunk_start && tA_ + 1 < chunk_end)                       \
          out[(size_t)b * T_FRAMES + tA_ + 1] = vy_;                             \
      }                                                                          \
    }                                                                            \
  } while (0)

// One sub-group: the CHAMPION (round-13) protocol, unchanged. Fill for the
// NEXT sub-buffer at subgroup start (LDGSTS hide under the whole consume
// phase), consume cur, WAIT0 + barrier (fill visible / cur consumed / tile
// written), reduce, barrier, swap. Consume dispatch is one uniform branch.
#define SUBGROUP(CM, CMNE, J0, TS)                                               \
  do {                                                                           \
    const int ts_ = (TS);                                                        \
    const bool es_ = (ts_ + 9 >= chunk_start) && (ts_ < chunk_end);              \
    const float* cur_p = stage + soff;                                           \
    if (ts_ + 10 < chunk_end)                                                    \
      FILL10(stage_a + 4u * (uint32_t)(soff ^ SUBF),                             \
             xb + (size_t)(ts_ + 10) * FROW);                                    \
    if (es_) { CM(J0); } else { CMNE(J0); }                                      \
    CP_WAIT0();                                                                  \
    __syncthreads();                                                             \
    if (es_) REDUCE5(ts_);                                                       \
    __syncthreads();                                                             \
    soff ^= SUBF;                                                                \
  } while (0)

__global__ __launch_bounds__(NTHREADS, 4)
void ltsf_kernel(const float* __restrict__ x, float* __restrict__ out,
                 const float cA) {
  __shared__ float  stage[2 * SUBF];     // two 10-frame sub-buffers (32.2 KB)
  __shared__ float2 buf2[BUFN];          // contrib tile (9 KB)

  const int unit = blockIdx.x;
  const int b = unit / CHUNKS;
  const int c = unit % CHUNKS;
  const int chunk_start = c * CHUNK;
  const int chunk_end = min(chunk_start + CHUNK, T_FRAMES);
  // >= 40 frames of halo, rounded DOWN to even (16B alignment of sub-buffers)
  const int t_begin = (c == 0) ? 0 : ((chunk_start - 40) & ~1);
  const bool t0block = (c == 0);

  const int tid  = threadIdx.x;
  const int f    = tid;
  const bool active = (f < F_BINS);
  const int lane = tid & 31;
  const int warp = tid >> 5;

  // per-bin scale: interior bins doubled (welch one-sided spectrum)
  const float Cf = (f == 0 || f == F_BINS - 1) ? cA : 2.0f * cA;
  const float L10m   = active ? LOG10_2 : 0.f;  // masks inactive contribs to 0
  const float rc30Lm = L10m * (1.0f / 30.0f);

  const int fsel = active ? f : 0;
  const int foff = 2 * fsel;
  const float* xb    = x + (size_t)b * T_FRAMES * FROW;
  const float* xlim  = x + (size_t)BATCH * T_FRAMES * FROW - 4;  // last 16B
  const float* xsafe = xlim + 4 - SUBF;   // max in-bounds fill base
  const uint32_t stage_a = (uint32_t)__cvta_generic_to_shared(stage);

  int soff = 0;        // stage buffer float offset, toggles 0 <-> SUBF

  // register-resident ring buffers (indices compile-time via full unroll)
  float ring_s[10];
  float ring_w[30];
  float sum_s = 0.f, sum_we = 0.f, sum_lw2 = 0.f;
#pragma unroll
  for (int i = 0; i < 10; i++) ring_s[i] = 0.f;
#pragma unroll
  for (int i = 0; i < 30; i++) ring_w[i] = 0.f;

  // ---- prologue: fill first sub-buffer, make it visible ----
  FILL10(stage_a, xb + (size_t)t_begin * FROW);
  CP_WAIT0();
  __syncthreads();

  // ---- warm group: frames t_begin..t_begin+29, ramp divisors ----
  SUBGROUP(CONSUME_WARM, CONSUME_WARM_NE, 0,  t_begin);
  SUBGROUP(CONSUME_WARM, CONSUME_WARM_NE, 10, t_begin + 10);
  SUBGROUP(CONSUME_WARM, CONSUME_WARM_NE, 20, t_begin + 20);

  // ---- steady groups (subgroups past chunk_end consume stale smem but
  //      never write: es_ is false there) ----
  for (int tb = t_begin + 30; tb < chunk_end; tb += 30) {
    SUBGROUP(CONSUME_STEADY, CONSUME_STEADY_NE, 0,  tb);
    SUBGROUP(CONSUME_STEADY, CONSUME_STEADY_NE, 10, tb + 10);
    SUBGROUP(CONSUME_STEADY, CONSUME_STEADY_NE, 20, tb + 20);
  }
}

extern "C" void kernel_launch(void* const* d_in, const int* in_sizes, int n_in,
                              void* d_out, int out_size) {
  (void)in_sizes; (void)n_in; (void)out_size;
  // hamming_sq_sum(25), periodic: sum((0.54 - 0.46*cos(2*pi*k/25))^2)
  double h = 0.0;
  for (int k = 0; k < 25; k++) {
    double w = 0.54 - 0.46 * cos(2.0 * M_PI * (double)k / 25.0);
    h += w * w;
  }
  // fold the /M (spectr) and /SAMPLE_RATE (welch) into one per-bin constant
  const float cA = (float)(h / 16000.0 / 10.0);

  const float* x = (const float*)d_in[0];
  float* out = (float*)d_out;
  ltsf_kernel<<<BATCH * CHUNKS, NTHREADS>>>(x, out, cA);
}